// round 12
// baseline (speedup 1.0000x reference)
#include <cuda_runtime.h>
#include <cuda_bf16.h>
#include <cuda_fp16.h>
#include <cstddef>
#include <cstdint>

#define N_NODES 50000
#define D_H 128
#define D_OUT 64
#define EPS 1e-5f
#define CAP 64   // max in-degree slots (Poisson(16): P(>=64) ~ 3e-22/node)
#define MT 3128  // ceil(50048/16) m-tiles in A-fragment images

// ===================== scratch =============================================
__device__ __half g_h128[(size_t)N_NODES * 128];  // gemm1/gemm2 out (fp16 gather feats)
__device__ __half g_h64[(size_t)N_NODES * 64];    // gemm3 out
// A-fragment images (hi/lo bf16), layout: [(mt*8+ks)*32+lane] -> uint4(a0,a1,a2,a3)
__device__ __align__(16) uint4 g_ahi[(size_t)MT * 8 * 32];
__device__ __align__(16) uint4 g_alo[(size_t)MT * 8 * 32];
__device__ float g_dinv[N_NODES];
__device__ int   g_cnt[N_NODES];
__device__ int   g_colp[(size_t)N_NODES * CAP];
__device__ int   g_nz;  // 1 -> indices are int32
// W images in mma B-fragment order: [hi: N*32 uint2][lo: N*32 uint2]
__device__ __align__(16) uint2 g_w1[2 * 128 * 32];
__device__ __align__(16) uint2 g_w2[2 * 128 * 32];
__device__ __align__(16) uint2 g_w3[2 * 64 * 32];

// ===================== bf16 split helper ====================================
__device__ __forceinline__ void bsplit(float f, unsigned short& h, unsigned short& l) {
    __nv_bfloat16 bh = __float2bfloat16(f);
    float r = f - __bfloat162float(bh);
    __nv_bfloat16 bl = __float2bfloat16(r);
    h = __bfloat16_as_ushort(bh);
    l = __bfloat16_as_ushort(bl);
}

// Write one row-lane's 4 cols (2 bf16x2 pairs) of hi/lo into the A-fragment
// images. Row r, lane owns cols 4*lane .. 4*lane+3  (pairs p0=2*lane, p0+1).
__device__ __forceinline__ void store_frag(int r, int lane,
                                           uint32_t hi0, uint32_t hi1,
                                           uint32_t lo0, uint32_t lo1) {
    int mt = r >> 4, rp = r & 15;
    int p0 = 2 * lane;
    int ks = p0 >> 3, q0 = p0 & 7;
    int c = ((rp < 8) ? 0 : 1) + ((q0 < 4) ? 0 : 2);  // q0 even -> both pairs same c
    int rr = rp & 7;
    int lf0 = rr * 4 + (q0 & 3);
    int lf1 = rr * 4 + ((q0 + 1) & 3);
    size_t base = (size_t)(mt * 8 + ks) * 32;
    uint32_t* H = (uint32_t*)g_ahi;
    uint32_t* L = (uint32_t*)g_alo;
    H[(base + lf0) * 4 + c] = hi0;
    H[(base + lf1) * 4 + c] = hi1;
    L[(base + lf0) * 4 + c] = lo0;
    L[(base + lf1) * 4 + c] = lo1;
}

// ===================== fused prep: init + prepW + detect ====================
__global__ void k_prep(const float* __restrict__ W1, const float* __restrict__ W2,
                       const float* __restrict__ W3, const int* __restrict__ ei) {
    int b = blockIdx.x;
    if (b < 196) {
        int i = b * 256 + threadIdx.x;
        if (i < N_NODES) g_cnt[i] = 0;
        return;
    }
    if (b < 199) {
        int w = b - 196;
        const float* W = (w == 0) ? W1 : (w == 1) ? W2 : W3;
        uint2* dst = (w == 0) ? g_w1 : (w == 1) ? g_w2 : g_w3;
        int N = (w == 2) ? 64 : 128;
        int perProd = N * 32;
        for (int e = threadIdx.x; e < 2 * perProd; e += blockDim.x) {
            int p = e / perProd;
            int rem = e % perProd;
            int ts = rem / 32;
            int l = rem % 32;
            int t = ts / 8, s = ts % 8;
            int n = t * 8 + (l >> 2);
            int k0 = s * 16 + (l & 3) * 2;
            unsigned short v[4], h, lo16;
            int ks[4] = {k0, k0 + 1, k0 + 8, k0 + 9};
#pragma unroll
            for (int q = 0; q < 4; q++) {
                bsplit(W[ks[q] * N + n], h, lo16);
                v[q] = p ? lo16 : h;
            }
            uint2 o;
            o.x = (uint32_t)v[0] | ((uint32_t)v[1] << 16);
            o.y = (uint32_t)v[2] | ((uint32_t)v[3] << 16);
            dst[e] = o;
        }
        return;
    }
    if (threadIdx.x < 32) {
        int lane = threadIdx.x;
        int nzl = (__ldg(&ei[2 * lane + 1]) != 0) | (__ldg(&ei[2 * (lane + 32) + 1]) != 0);
        unsigned m = __ballot_sync(0xFFFFFFFFu, nzl);
        if (lane == 0) g_nz = (m != 0) ? 1 : 0;
    }
}

// x (fp32) -> A-fragment images. One warp per row.
__global__ void k_conv(const float* __restrict__ x) {
    int w = (blockIdx.x * blockDim.x + threadIdx.x) >> 5;
    int lane = threadIdx.x & 31;
    if (w >= N_NODES) return;
    float4 v = __ldg((const float4*)(x + (size_t)w * 128) + lane);
    unsigned short h0, l0, h1, l1, h2, l2, h3, l3;
    bsplit(v.x, h0, l0);
    bsplit(v.y, h1, l1);
    bsplit(v.z, h2, l2);
    bsplit(v.w, h3, l3);
    store_frag(w, lane,
               (uint32_t)h0 | ((uint32_t)h1 << 16), (uint32_t)h2 | ((uint32_t)h3 << 16),
               (uint32_t)l0 | ((uint32_t)l1 << 16), (uint32_t)l2 | ((uint32_t)l3 << 16));
}

__device__ __forceinline__ int load_idx(const void* p, long long i, int is64) {
    return is64 ? (int)((const long long*)p)[i] : ((const int*)p)[i];
}

__global__ void k_fillpad(const void* __restrict__ idx, int E) {
    int e = blockIdx.x * blockDim.x + threadIdx.x;
    if (e >= E) return;
    int is64 = (g_nz == 0);
    int s = load_idx(idx, e, is64);
    int d = load_idx(idx, (long long)E + e, is64);
    int pos = atomicAdd(&g_cnt[d], 1);
    if (pos < CAP) g_colp[(size_t)d * CAP + pos] = s;
}

__global__ void k_dinv() {
    int i = blockIdx.x * blockDim.x + threadIdx.x;
    if (i < N_NODES) g_dinv[i] = rsqrtf((float)g_cnt[i] + 1.0f);
}

// ===================== mma helper ===========================================
__device__ __forceinline__ void mma16816(float& d0, float& d1, float& d2, float& d3,
                                         uint32_t a0, uint32_t a1, uint32_t a2, uint32_t a3,
                                         uint32_t b0, uint32_t b1) {
    asm volatile(
        "mma.sync.aligned.m16n8k16.row.col.f32.bf16.bf16.f32 "
        "{%0,%1,%2,%3}, {%4,%5,%6,%7}, {%8,%9}, {%0,%1,%2,%3};"
        : "+f"(d0), "+f"(d1), "+f"(d2), "+f"(d3)
        : "r"(a0), "r"(a1), "r"(a2), "r"(a3), "r"(b0), "r"(b1));
}

// ===================== fragment-image GEMM (no smem, no LDSM) ===============
// C[M,N] = A[M,128] @ W[128,N]; A from g_ahi/g_alo fragment images.
template <int N>
__global__ void __launch_bounds__(256, 2) k_gemm_frag(const uint2* __restrict__ wimg,
                                                      __half* __restrict__ C) {
    constexpr int NSUB = N / 16;
    int tid = threadIdx.x;
    int lane = tid & 31;
    int wid = tid >> 5;
    int wm = wid & 3;
    int wn = wid >> 2;
    int rowBase = blockIdx.x * 128;
    int mtBase = blockIdx.x * 8 + wm * 2;

    const uint2* Bh = wimg;
    const uint2* Bl = wimg + N * 32;

    float acc[2][NSUB][4];
#pragma unroll
    for (int i = 0; i < 2; i++)
#pragma unroll
        for (int j = 0; j < NSUB; j++)
#pragma unroll
            for (int q = 0; q < 4; q++) acc[i][j][q] = 0.f;

#pragma unroll
    for (int ks = 0; ks < 8; ks++) {
        uint4 ah[2], al[2];
#pragma unroll
        for (int i = 0; i < 2; i++) {
            size_t idx = (size_t)((mtBase + i) * 8 + ks) * 32 + lane;
            ah[i] = __ldg(&g_ahi[idx]);
            al[i] = __ldg(&g_alo[idx]);
        }
#pragma unroll
        for (int j = 0; j < NSUB; j++) {
            int ntile = wn * NSUB + j;
            int bidx = (ntile * 8 + ks) * 32 + lane;
            uint2 bh = __ldg(&Bh[bidx]);
            uint2 bl = __ldg(&Bl[bidx]);
#pragma unroll
            for (int i = 0; i < 2; i++) {
                mma16816(acc[i][j][0], acc[i][j][1], acc[i][j][2], acc[i][j][3],
                         ah[i].x, ah[i].y, ah[i].z, ah[i].w, bh.x, bh.y);
                mma16816(acc[i][j][0], acc[i][j][1], acc[i][j][2], acc[i][j][3],
                         ah[i].x, ah[i].y, ah[i].z, ah[i].w, bl.x, bl.y);
                mma16816(acc[i][j][0], acc[i][j][1], acc[i][j][2], acc[i][j][3],
                         al[i].x, al[i].y, al[i].z, al[i].w, bh.x, bh.y);
            }
        }
    }

#pragma unroll
    for (int i = 0; i < 2; i++) {
        int r0 = rowBase + wm * 32 + i * 16 + (lane >> 2);
#pragma unroll
        for (int j = 0; j < NSUB; j++) {
            int col = wn * (N / 2) + j * 8 + (lane & 3) * 2;
            if (r0 < N_NODES)
                *(__half2*)&C[(size_t)r0 * N + col] = __floats2half2_rn(acc[i][j][0], acc[i][j][1]);
            if (r0 + 8 < N_NODES)
                *(__half2*)&C[(size_t)(r0 + 8) * N + col] = __floats2half2_rn(acc[i][j][2], acc[i][j][3]);
        }
    }
}

// ===================== aggregation (fp16 gather, fp32 math) =================
__device__ __forceinline__ void h4_to_f(const uint2 u, float* f) {
    float2 a = __half22float2(*(const __half2*)&u.x);
    float2 b = __half22float2(*(const __half2*)&u.y);
    f[0] = a.x; f[1] = a.y; f[2] = b.x; f[3] = b.y;
}

// FRAG_OUT: write hi/lo A-fragment images (next gemm input); else fp32 out.
template <int COLS, bool RELU_LN, bool FRAG_OUT>
__global__ void k_agg(const __half* __restrict__ xw, const float* __restrict__ bias,
                      const float* __restrict__ gamma, const float* __restrict__ beta,
                      float* __restrict__ out) {
    int w = (blockIdx.x * blockDim.x + threadIdx.x) >> 5;
    int lane = threadIdx.x & 31;
    if (w >= N_NODES) return;
    constexpr int V = COLS / 32;  // 4 or 2
    float di = g_dinv[w];
    int cnt = __ldg(&g_cnt[w]);
    int end = (cnt < CAP) ? cnt : CAP;
    const int* clist = g_colp + (size_t)w * CAP;

    float acc[V];
#pragma unroll
    for (int j = 0; j < V; j++) acc[j] = 0.f;

    int k = 0;
    for (; k + 2 <= end; k += 2) {
        int s0 = __ldg(&clist[k]);
        int s1 = __ldg(&clist[k + 1]);
        float w0 = __ldg(&g_dinv[s0]);
        float w1 = __ldg(&g_dinv[s1]);
        if (V == 4) {
            uint2 u0 = __ldg((const uint2*)(xw + (size_t)s0 * COLS) + lane);
            uint2 u1 = __ldg((const uint2*)(xw + (size_t)s1 * COLS) + lane);
            float f0[4], f1[4];
            h4_to_f(u0, f0);
            h4_to_f(u1, f1);
#pragma unroll
            for (int j = 0; j < 4; j++) acc[j] += w0 * f0[j] + w1 * f1[j];
        } else {
            uint32_t u0 = __ldg((const uint32_t*)(xw + (size_t)s0 * COLS) + lane);
            uint32_t u1 = __ldg((const uint32_t*)(xw + (size_t)s1 * COLS) + lane);
            float2 f0 = __half22float2(*(const __half2*)&u0);
            float2 f1 = __half22float2(*(const __half2*)&u1);
            acc[0] += w0 * f0.x + w1 * f1.x;
            acc[1] += w0 * f0.y + w1 * f1.y;
        }
    }
    if (k < end) {
        int s0 = __ldg(&clist[k]);
        float w0 = __ldg(&g_dinv[s0]);
        if (V == 4) {
            uint2 u0 = __ldg((const uint2*)(xw + (size_t)s0 * COLS) + lane);
            float f0[4];
            h4_to_f(u0, f0);
#pragma unroll
            for (int j = 0; j < 4; j++) acc[j] += w0 * f0[j];
        } else {
            uint32_t u0 = __ldg((const uint32_t*)(xw + (size_t)s0 * COLS) + lane);
            float2 f0 = __half22float2(*(const __half2*)&u0);
            acc[0] += w0 * f0.x;
            acc[1] += w0 * f0.y;
        }
    }

    float di2 = di * di;
    float x[V];
    if (V == 4) {
        uint2 us = __ldg((const uint2*)(xw + (size_t)w * COLS) + lane);
        float fs[4];
        h4_to_f(us, fs);
#pragma unroll
        for (int j = 0; j < 4; j++) x[j] = acc[j] * di + di2 * fs[j];
    } else {
        uint32_t us = __ldg((const uint32_t*)(xw + (size_t)w * COLS) + lane);
        float2 fs = __half22float2(*(const __half2*)&us);
        x[0] = acc[0] * di + di2 * fs.x;
        x[1] = acc[1] * di + di2 * fs.y;
    }
#pragma unroll
    for (int j = 0; j < V; j++) x[j] += __ldg(&bias[lane * V + j]);

    if (RELU_LN) {
#pragma unroll
        for (int j = 0; j < V; j++) x[j] = fmaxf(x[j], 0.f);
        float s = 0.f, s2 = 0.f;
#pragma unroll
        for (int j = 0; j < V; j++) { s += x[j]; s2 += x[j] * x[j]; }
#pragma unroll
        for (int o = 16; o > 0; o >>= 1) {
            s += __shfl_xor_sync(0xFFFFFFFFu, s, o);
            s2 += __shfl_xor_sync(0xFFFFFFFFu, s2, o);
        }
        float mu = s * (1.0f / COLS);
        float var = s2 * (1.0f / COLS) - mu * mu;
        float inv = rsqrtf(var + EPS);
#pragma unroll
        for (int j = 0; j < V; j++)
            x[j] = (x[j] - mu) * inv * __ldg(&gamma[lane * V + j]) + __ldg(&beta[lane * V + j]);
    }

    if (FRAG_OUT) {
        unsigned short h0, l0, h1, l1, h2, l2, h3, l3;
        bsplit(x[0], h0, l0);
        bsplit(x[1], h1, l1);
        bsplit(x[2], h2, l2);
        bsplit(x[3], h3, l3);
        store_frag(w, lane,
                   (uint32_t)h0 | ((uint32_t)h1 << 16), (uint32_t)h2 | ((uint32_t)h3 << 16),
                   (uint32_t)l0 | ((uint32_t)l1 << 16), (uint32_t)l2 | ((uint32_t)l3 << 16));
    } else {
        if (V == 4) {
            float4 v = make_float4(x[0], x[1], x[2], x[3]);
            *((float4*)(out + (size_t)w * COLS) + lane) = v;
        } else {
            float2 v = make_float2(x[0], x[1]);
            *((float2*)(out + (size_t)w * COLS) + lane) = v;
        }
    }
}

// ===================== launch ===============================================
extern "C" void kernel_launch(void* const* d_in, const int* in_sizes, int n_in,
                              void* d_out, int out_size) {
    const float* x  = (const float*)d_in[0];
    const void*  ei = d_in[1];
    const float* W1 = (const float*)d_in[2];
    const float* b1 = (const float*)d_in[3];
    const float* W2 = (const float*)d_in[4];
    const float* b2 = (const float*)d_in[5];
    const float* W3 = (const float*)d_in[6];
    const float* b3 = (const float*)d_in[7];
    const float* g1 = (const float*)d_in[8];
    const float* be1 = (const float*)d_in[9];
    const float* g2 = (const float*)d_in[10];
    const float* be2 = (const float*)d_in[11];
    float* out = (float*)d_out;
    int E = in_sizes[1] / 2;

    __half *hX, *hC;
    uint2 *w1i, *w2i, *w3i;
    cudaGetSymbolAddress((void**)&hX, g_h128);
    cudaGetSymbolAddress((void**)&hC, g_h64);
    cudaGetSymbolAddress((void**)&w1i, g_w1);
    cudaGetSymbolAddress((void**)&w2i, g_w2);
    cudaGetSymbolAddress((void**)&w3i, g_w3);

    cudaStream_t s2;
    cudaStreamCreateWithFlags(&s2, cudaStreamNonBlocking);
    cudaEvent_t evFork, evJoin;
    cudaEventCreateWithFlags(&evFork, cudaEventDisableTiming);
    cudaEventCreateWithFlags(&evJoin, cudaEventDisableTiming);

    int gemmGrid = (N_NODES + 127) / 128;  // 391
    int aggGrid = (N_NODES + 7) / 8;       // 6250

    // prep feeds both branches (cnt init for adjacency, W images for gemm)
    k_prep<<<200, 256>>>(W1, W2, W3, (const int*)ei);
    cudaEventRecord(evFork, 0);
    cudaStreamWaitEvent(s2, evFork, 0);

    // branch A (s2): single-pass padded adjacency + dinv
    k_fillpad<<<(E + 255) / 256, 256, 0, s2>>>(ei, E);
    k_dinv<<<(N_NODES + 255) / 256, 256, 0, s2>>>();
    cudaEventRecord(evJoin, s2);

    // branch B (default): x -> fragment images, then gemm1
    k_conv<<<aggGrid, 256>>>(x);
    k_gemm_frag<128><<<gemmGrid, 256>>>(w1i, hX);

    // join: agg1 needs adjacency + gemm1
    cudaStreamWaitEvent(0, evJoin, 0);
    k_agg<128, true, true><<<aggGrid, 256>>>(hX, b1, g1, be1, nullptr);
    // layer 2
    k_gemm_frag<128><<<gemmGrid, 256>>>(w2i, hX);
    k_agg<128, true, true><<<aggGrid, 256>>>(hX, b2, g2, be2, nullptr);
    // layer 3
    k_gemm_frag<64><<<gemmGrid, 256>>>(w3i, hC);
    k_agg<64, false, false><<<aggGrid, 256>>>(hC, b3, nullptr, nullptr, out);
}

// round 13
// speedup vs baseline: 1.0275x; 1.0275x over previous
#include <cuda_runtime.h>
#include <cuda_bf16.h>
#include <cuda_fp16.h>
#include <cstddef>
#include <cstdint>

#define N_NODES 50000
#define D_H 128
#define D_OUT 64
#define EPS 1e-5f
#define CAP 64   // max in-degree slots (Poisson(16): P(>=64) ~ 3e-22/node)
#define MT 3128  // m-tiles allocated (3125 used; gemm grid reads to 3127, zeros)
#define SSTR 68  // smem word stride: 68%32=4 -> phase-2 reads conflict-free

// ===================== scratch =============================================
__device__ __half g_h128[(size_t)N_NODES * 128];  // gemm1/gemm2 out (fp16 gather feats)
__device__ __half g_h64[(size_t)N_NODES * 64];    // gemm3 out
// A-fragment images (hi/lo bf16): [(mt*8+ks)*32+lane] -> uint4(a0,a1,a2,a3)
__device__ __align__(16) uint4 g_ahi[(size_t)MT * 8 * 32];
__device__ __align__(16) uint4 g_alo[(size_t)MT * 8 * 32];
__device__ float g_dinv[N_NODES];
__device__ int   g_cnt[N_NODES];
__device__ int   g_colp[(size_t)N_NODES * CAP];
__device__ int   g_nz;  // 1 -> indices are int32
// W images in mma B-fragment order: [hi: N*32 uint2][lo: N*32 uint2]
__device__ __align__(16) uint2 g_w1[2 * 128 * 32];
__device__ __align__(16) uint2 g_w2[2 * 128 * 32];
__device__ __align__(16) uint2 g_w3[2 * 64 * 32];

// ===================== bf16 split helper ====================================
__device__ __forceinline__ void bsplit(float f, unsigned short& h, unsigned short& l) {
    __nv_bfloat16 bh = __float2bfloat16(f);
    float r = f - __bfloat162float(bh);
    __nv_bfloat16 bl = __float2bfloat16(r);
    h = __bfloat16_as_ushort(bh);
    l = __bfloat16_as_ushort(bl);
}

// Compose one uint4 A-fragment (ks, lf) from a 16-row smem pair-word image.
__device__ __forceinline__ uint4 frag_from_smem(const uint32_t* S, int ks, int lf) {
    int rr = lf >> 2, tg = lf & 3;
    uint4 v;
    v.x = S[rr * SSTR + ks * 8 + tg];
    v.y = S[(rr + 8) * SSTR + ks * 8 + tg];
    v.z = S[rr * SSTR + ks * 8 + 4 + tg];
    v.w = S[(rr + 8) * SSTR + ks * 8 + 4 + tg];
    return v;
}

// ===================== fused prep: init + prepW + detect ====================
__global__ void k_prep(const float* __restrict__ W1, const float* __restrict__ W2,
                       const float* __restrict__ W3, const int* __restrict__ ei) {
    int b = blockIdx.x;
    if (b < 196) {
        int i = b * 256 + threadIdx.x;
        if (i < N_NODES) g_cnt[i] = 0;
        return;
    }
    if (b < 199) {
        int w = b - 196;
        const float* W = (w == 0) ? W1 : (w == 1) ? W2 : W3;
        uint2* dst = (w == 0) ? g_w1 : (w == 1) ? g_w2 : g_w3;
        int N = (w == 2) ? 64 : 128;
        int perProd = N * 32;
        for (int e = threadIdx.x; e < 2 * perProd; e += blockDim.x) {
            int p = e / perProd;
            int rem = e % perProd;
            int ts = rem / 32;
            int l = rem % 32;
            int t = ts / 8, s = ts % 8;
            int n = t * 8 + (l >> 2);
            int k0 = s * 16 + (l & 3) * 2;
            unsigned short v[4], h, lo16;
            int ks[4] = {k0, k0 + 1, k0 + 8, k0 + 9};
#pragma unroll
            for (int q = 0; q < 4; q++) {
                bsplit(W[ks[q] * N + n], h, lo16);
                v[q] = p ? lo16 : h;
            }
            uint2 o;
            o.x = (uint32_t)v[0] | ((uint32_t)v[1] << 16);
            o.y = (uint32_t)v[2] | ((uint32_t)v[3] << 16);
            dst[e] = o;
        }
        return;
    }
    if (threadIdx.x < 32) {
        int lane = threadIdx.x;
        int nzl = (__ldg(&ei[2 * lane + 1]) != 0) | (__ldg(&ei[2 * (lane + 32) + 1]) != 0);
        unsigned m = __ballot_sync(0xFFFFFFFFu, nzl);
        if (lane == 0) g_nz = (m != 0) ? 1 : 0;
    }
}

// x (fp32) -> A-fragment images; smem-staged, coalesced in and out.
// Block: 256 threads, 32 rows (2 m-tiles).
__global__ void k_conv(const float* __restrict__ x) {
    __shared__ uint32_t SH[32 * SSTR];
    __shared__ uint32_t SL[32 * SSTR];
    int t = threadIdx.x;
    int rowBase = blockIdx.x * 32;
    // phase 1: coalesced loads + convert into smem
#pragma unroll
    for (int i = 0; i < 4; i++) {
        int flat = i * 256 + t;          // 0..1023
        int r = flat >> 5;               // 0..31
        int q = flat & 31;               // float4 index
        int gr = rowBase + r;
        float4 v = (gr < N_NODES) ? __ldg((const float4*)(x + (size_t)gr * 128) + q)
                                  : make_float4(0.f, 0.f, 0.f, 0.f);
        unsigned short h0, l0, h1, l1, h2, l2, h3, l3;
        bsplit(v.x, h0, l0);
        bsplit(v.y, h1, l1);
        bsplit(v.z, h2, l2);
        bsplit(v.w, h3, l3);
        SH[r * SSTR + 2 * q]     = (uint32_t)h0 | ((uint32_t)h1 << 16);
        SH[r * SSTR + 2 * q + 1] = (uint32_t)h2 | ((uint32_t)h3 << 16);
        SL[r * SSTR + 2 * q]     = (uint32_t)l0 | ((uint32_t)l1 << 16);
        SL[r * SSTR + 2 * q + 1] = (uint32_t)l2 | ((uint32_t)l3 << 16);
    }
    __syncthreads();
    // phase 2: coalesced fragment writes (2 mts x 8 ks x 32 lf, hi+lo)
#pragma unroll
    for (int j = 0; j < 2; j++) {
        int idx = j * 256 + t;           // 0..511
        int mtL = idx >> 8;              // 0..1 -- wait 512/256: idx>>8 gives 0..1
        int rem = idx & 255;
        int ks = rem >> 5, lf = rem & 31;
        int mt = blockIdx.x * 2 + mtL;
        if (mt < MT) {
            size_t gidx = (size_t)(mt * 8 + ks) * 32 + lf;
            g_ahi[gidx] = frag_from_smem(SH + mtL * 16 * SSTR, ks, lf);
            g_alo[gidx] = frag_from_smem(SL + mtL * 16 * SSTR, ks, lf);
        }
    }
}

__device__ __forceinline__ int load_idx(const void* p, long long i, int is64) {
    return is64 ? (int)((const long long*)p)[i] : ((const int*)p)[i];
}

__global__ void k_fillpad(const void* __restrict__ idx, int E) {
    int e = blockIdx.x * blockDim.x + threadIdx.x;
    if (e >= E) return;
    int is64 = (g_nz == 0);
    int s = load_idx(idx, e, is64);
    int d = load_idx(idx, (long long)E + e, is64);
    int pos = atomicAdd(&g_cnt[d], 1);
    if (pos < CAP) g_colp[(size_t)d * CAP + pos] = s;
}

__global__ void k_dinv() {
    int i = blockIdx.x * blockDim.x + threadIdx.x;
    if (i < N_NODES) g_dinv[i] = rsqrtf((float)g_cnt[i] + 1.0f);
}

// ===================== mma helper ===========================================
__device__ __forceinline__ void mma16816(float& d0, float& d1, float& d2, float& d3,
                                         uint32_t a0, uint32_t a1, uint32_t a2, uint32_t a3,
                                         uint32_t b0, uint32_t b1) {
    asm volatile(
        "mma.sync.aligned.m16n8k16.row.col.f32.bf16.bf16.f32 "
        "{%0,%1,%2,%3}, {%4,%5,%6,%7}, {%8,%9}, {%0,%1,%2,%3};"
        : "+f"(d0), "+f"(d1), "+f"(d2), "+f"(d3)
        : "r"(a0), "r"(a1), "r"(a2), "r"(a3), "r"(b0), "r"(b1));
}

// ===================== fragment-image GEMM (no smem, no LDSM) ===============
template <int N>
__global__ void __launch_bounds__(256, 2) k_gemm_frag(const uint2* __restrict__ wimg,
                                                      __half* __restrict__ C) {
    constexpr int NSUB = N / 16;
    int tid = threadIdx.x;
    int lane = tid & 31;
    int wid = tid >> 5;
    int wm = wid & 3;
    int wn = wid >> 2;
    int rowBase = blockIdx.x * 128;
    int mtBase = blockIdx.x * 8 + wm * 2;

    const uint2* Bh = wimg;
    const uint2* Bl = wimg + N * 32;

    float acc[2][NSUB][4];
#pragma unroll
    for (int i = 0; i < 2; i++)
#pragma unroll
        for (int j = 0; j < NSUB; j++)
#pragma unroll
            for (int q = 0; q < 4; q++) acc[i][j][q] = 0.f;

#pragma unroll
    for (int ks = 0; ks < 8; ks++) {
        uint4 ah[2], al[2];
#pragma unroll
        for (int i = 0; i < 2; i++) {
            size_t idx = (size_t)((mtBase + i) * 8 + ks) * 32 + lane;
            ah[i] = __ldg(&g_ahi[idx]);
            al[i] = __ldg(&g_alo[idx]);
        }
#pragma unroll
        for (int j = 0; j < NSUB; j++) {
            int ntile = wn * NSUB + j;
            int bidx = (ntile * 8 + ks) * 32 + lane;
            uint2 bh = __ldg(&Bh[bidx]);
            uint2 bl = __ldg(&Bl[bidx]);
#pragma unroll
            for (int i = 0; i < 2; i++) {
                mma16816(acc[i][j][0], acc[i][j][1], acc[i][j][2], acc[i][j][3],
                         ah[i].x, ah[i].y, ah[i].z, ah[i].w, bh.x, bh.y);
                mma16816(acc[i][j][0], acc[i][j][1], acc[i][j][2], acc[i][j][3],
                         ah[i].x, ah[i].y, ah[i].z, ah[i].w, bl.x, bl.y);
                mma16816(acc[i][j][0], acc[i][j][1], acc[i][j][2], acc[i][j][3],
                         al[i].x, al[i].y, al[i].z, al[i].w, bh.x, bh.y);
            }
        }
    }

#pragma unroll
    for (int i = 0; i < 2; i++) {
        int r0 = rowBase + wm * 32 + i * 16 + (lane >> 2);
#pragma unroll
        for (int j = 0; j < NSUB; j++) {
            int col = wn * (N / 2) + j * 8 + (lane & 3) * 2;
            if (r0 < N_NODES)
                *(__half2*)&C[(size_t)r0 * N + col] = __floats2half2_rn(acc[i][j][0], acc[i][j][1]);
            if (r0 + 8 < N_NODES)
                *(__half2*)&C[(size_t)(r0 + 8) * N + col] = __floats2half2_rn(acc[i][j][2], acc[i][j][3]);
        }
    }
}

// ===================== aggregation (fp16 gather, fp32 math) =================
__device__ __forceinline__ void h4_to_f(const uint2 u, float* f) {
    float2 a = __half22float2(*(const __half2*)&u.x);
    float2 b = __half22float2(*(const __half2*)&u.y);
    f[0] = a.x; f[1] = a.y; f[2] = b.x; f[3] = b.y;
}

// Gather+scale+bias(+relu+LN) for one row per warp; returns x[V].
template <int COLS>
__device__ __forceinline__ void agg_row(int w, int lane, const __half* __restrict__ xw,
                                        const float* __restrict__ bias, float* x) {
    constexpr int V = COLS / 32;
    float di = g_dinv[w];
    int cnt = __ldg(&g_cnt[w]);
    int end = (cnt < CAP) ? cnt : CAP;
    const int* clist = g_colp + (size_t)w * CAP;

    float acc[V];
#pragma unroll
    for (int j = 0; j < V; j++) acc[j] = 0.f;

    int k = 0;
    for (; k + 2 <= end; k += 2) {
        int s0 = __ldg(&clist[k]);
        int s1 = __ldg(&clist[k + 1]);
        float w0 = __ldg(&g_dinv[s0]);
        float w1 = __ldg(&g_dinv[s1]);
        if (V == 4) {
            uint2 u0 = __ldg((const uint2*)(xw + (size_t)s0 * COLS) + lane);
            uint2 u1 = __ldg((const uint2*)(xw + (size_t)s1 * COLS) + lane);
            float f0[4], f1[4];
            h4_to_f(u0, f0);
            h4_to_f(u1, f1);
#pragma unroll
            for (int j = 0; j < 4; j++) acc[j] += w0 * f0[j] + w1 * f1[j];
        } else {
            uint32_t u0 = __ldg((const uint32_t*)(xw + (size_t)s0 * COLS) + lane);
            uint32_t u1 = __ldg((const uint32_t*)(xw + (size_t)s1 * COLS) + lane);
            float2 f0 = __half22float2(*(const __half2*)&u0);
            float2 f1 = __half22float2(*(const __half2*)&u1);
            acc[0] += w0 * f0.x + w1 * f1.x;
            acc[1] += w0 * f0.y + w1 * f1.y;
        }
    }
    if (k < end) {
        int s0 = __ldg(&clist[k]);
        float w0 = __ldg(&g_dinv[s0]);
        if (V == 4) {
            uint2 u0 = __ldg((const uint2*)(xw + (size_t)s0 * COLS) + lane);
            float f0[4];
            h4_to_f(u0, f0);
#pragma unroll
            for (int j = 0; j < 4; j++) acc[j] += w0 * f0[j];
        } else {
            uint32_t u0 = __ldg((const uint32_t*)(xw + (size_t)s0 * COLS) + lane);
            float2 f0 = __half22float2(*(const __half2*)&u0);
            acc[0] += w0 * f0.x;
            acc[1] += w0 * f0.y;
        }
    }

    float di2 = di * di;
    if (V == 4) {
        uint2 us = __ldg((const uint2*)(xw + (size_t)w * COLS) + lane);
        float fs[4];
        h4_to_f(us, fs);
#pragma unroll
        for (int j = 0; j < 4; j++) x[j] = acc[j] * di + di2 * fs[j];
    } else {
        uint32_t us = __ldg((const uint32_t*)(xw + (size_t)w * COLS) + lane);
        float2 fs = __half22float2(*(const __half2*)&us);
        x[0] = acc[0] * di + di2 * fs.x;
        x[1] = acc[1] * di + di2 * fs.y;
    }
#pragma unroll
    for (int j = 0; j < V; j++) x[j] += __ldg(&bias[lane * V + j]);
}

__device__ __forceinline__ void relu_ln_128(float* x, int lane,
                                            const float* __restrict__ gamma,
                                            const float* __restrict__ beta) {
#pragma unroll
    for (int j = 0; j < 4; j++) x[j] = fmaxf(x[j], 0.f);
    float s = 0.f, s2 = 0.f;
#pragma unroll
    for (int j = 0; j < 4; j++) { s += x[j]; s2 += x[j] * x[j]; }
#pragma unroll
    for (int o = 16; o > 0; o >>= 1) {
        s += __shfl_xor_sync(0xFFFFFFFFu, s, o);
        s2 += __shfl_xor_sync(0xFFFFFFFFu, s2, o);
    }
    float mu = s * (1.0f / 128.0f);
    float var = s2 * (1.0f / 128.0f) - mu * mu;
    float inv = rsqrtf(var + EPS);
#pragma unroll
    for (int j = 0; j < 4; j++)
        x[j] = (x[j] - mu) * inv * __ldg(&gamma[lane * 4 + j]) + __ldg(&beta[lane * 4 + j]);
}

// FRAG_OUT agg: 512 threads = 16 rows = one m-tile; smem-staged coalesced
// fragment writes (hi by threads 0-255, lo by 256-511).
__global__ void __launch_bounds__(512) k_agg_frag(const __half* __restrict__ xw,
                                                  const float* __restrict__ bias,
                                                  const float* __restrict__ gamma,
                                                  const float* __restrict__ beta) {
    __shared__ uint32_t SH[16 * SSTR];
    __shared__ uint32_t SL[16 * SSTR];
    int tid = threadIdx.x;
    int lane = tid & 31;
    int wid = tid >> 5;          // 0..15 = row-in-tile
    int w = blockIdx.x * 16 + wid;  // 3125*16 = 50000 exactly

    float x[4];
    agg_row<128>(w, lane, xw, bias, x);
    relu_ln_128(x, lane, gamma, beta);

    unsigned short h0, l0, h1, l1, h2, l2, h3, l3;
    bsplit(x[0], h0, l0);
    bsplit(x[1], h1, l1);
    bsplit(x[2], h2, l2);
    bsplit(x[3], h3, l3);
    SH[wid * SSTR + 2 * lane]     = (uint32_t)h0 | ((uint32_t)h1 << 16);
    SH[wid * SSTR + 2 * lane + 1] = (uint32_t)h2 | ((uint32_t)h3 << 16);
    SL[wid * SSTR + 2 * lane]     = (uint32_t)l0 | ((uint32_t)l1 << 16);
    SL[wid * SSTR + 2 * lane + 1] = (uint32_t)l2 | ((uint32_t)l3 << 16);
    __syncthreads();

    int mt = blockIdx.x;
    int half = tid >> 8;          // 0: hi, 1: lo
    int rem = tid & 255;
    int ks = rem >> 5, lf = rem & 31;
    size_t gidx = (size_t)(mt * 8 + ks) * 32 + lf;
    if (half == 0)
        g_ahi[gidx] = frag_from_smem(SH, ks, lf);
    else
        g_alo[gidx] = frag_from_smem(SL, ks, lf);
}

// final agg (64 cols, fp32 out), 256 threads as before
__global__ void k_agg_out(const __half* __restrict__ xw, const float* __restrict__ bias,
                          float* __restrict__ out) {
    int w = (blockIdx.x * blockDim.x + threadIdx.x) >> 5;
    int lane = threadIdx.x & 31;
    if (w >= N_NODES) return;
    float x[2];
    agg_row<64>(w, lane, xw, bias, x);
    *((float2*)(out + (size_t)w * 64) + lane) = make_float2(x[0], x[1]);
}

// ===================== launch ===============================================
extern "C" void kernel_launch(void* const* d_in, const int* in_sizes, int n_in,
                              void* d_out, int out_size) {
    const float* x  = (const float*)d_in[0];
    const void*  ei = d_in[1];
    const float* W1 = (const float*)d_in[2];
    const float* b1 = (const float*)d_in[3];
    const float* W2 = (const float*)d_in[4];
    const float* b2 = (const float*)d_in[5];
    const float* W3 = (const float*)d_in[6];
    const float* b3 = (const float*)d_in[7];
    const float* g1 = (const float*)d_in[8];
    const float* be1 = (const float*)d_in[9];
    const float* g2 = (const float*)d_in[10];
    const float* be2 = (const float*)d_in[11];
    float* out = (float*)d_out;
    int E = in_sizes[1] / 2;

    __half *hX, *hC;
    uint2 *w1i, *w2i, *w3i;
    cudaGetSymbolAddress((void**)&hX, g_h128);
    cudaGetSymbolAddress((void**)&hC, g_h64);
    cudaGetSymbolAddress((void**)&w1i, g_w1);
    cudaGetSymbolAddress((void**)&w2i, g_w2);
    cudaGetSymbolAddress((void**)&w3i, g_w3);

    cudaStream_t s2;
    cudaStreamCreateWithFlags(&s2, cudaStreamNonBlocking);
    cudaEvent_t evFork, evJoin;
    cudaEventCreateWithFlags(&evFork, cudaEventDisableTiming);
    cudaEventCreateWithFlags(&evJoin, cudaEventDisableTiming);

    int gemmGrid = (N_NODES + 127) / 128;  // 391

    // prep feeds both branches (cnt init for adjacency, W images for gemm)
    k_prep<<<200, 256>>>(W1, W2, W3, (const int*)ei);
    cudaEventRecord(evFork, 0);
    cudaStreamWaitEvent(s2, evFork, 0);

    // branch A (s2): single-pass padded adjacency + dinv
    k_fillpad<<<(E + 255) / 256, 256, 0, s2>>>(ei, E);
    k_dinv<<<(N_NODES + 255) / 256, 256, 0, s2>>>();
    cudaEventRecord(evJoin, s2);

    // branch B (default): x -> fragment images (smem-staged), then gemm1
    k_conv<<<1563, 256>>>(x);
    k_gemm_frag<128><<<gemmGrid, 256>>>(w1i, hX);

    // join: agg1 needs adjacency + gemm1
    cudaStreamWaitEvent(0, evJoin, 0);
    k_agg_frag<<<3125, 512>>>(hX, b1, g1, be1);
    // layer 2
    k_gemm_frag<128><<<gemmGrid, 256>>>(w2i, hX);
    k_agg_frag<<<3125, 512>>>(hX, b2, g2, be2);
    // layer 3
    k_gemm_frag<64><<<gemmGrid, 256>>>(w3i, hC);
    k_agg_out<<<6250, 256>>>(hC, b3, out);
}

// round 14
// speedup vs baseline: 1.0299x; 1.0023x over previous
#include <cuda_runtime.h>
#include <cuda_bf16.h>
#include <cuda_fp16.h>
#include <cstddef>
#include <cstdint>

#define N_NODES 50000
#define D_H 128
#define D_OUT 64
#define EPS 1e-5f
#define CAP 64   // max in-degree slots (Poisson(16): P(>=64) ~ 3e-22/node)
#define MT 3128  // m-tiles allocated (3125 used)
#define SSTR 68  // smem word stride: conflict-free phase-2 reads

// ===================== scratch =============================================
__device__ __half g_h128[(size_t)N_NODES * 128];  // gemm1/gemm2 out (fp16 gather feats)
__device__ __half g_h64[(size_t)N_NODES * 64];    // gemm3 out
// A-fragment images (hi/lo bf16): [(mt*8+ks)*32+lane] -> uint4(a0,a1,a2,a3)
__device__ __align__(16) uint4 g_ahi[(size_t)MT * 8 * 32];
__device__ __align__(16) uint4 g_alo[(size_t)MT * 8 * 32];
__device__ float g_dinv[N_NODES];
__device__ int   g_cnt[N_NODES];
__device__ int   g_colp[(size_t)N_NODES * CAP];
__device__ int   g_nz;  // 1 -> indices are int32
// W images in mma B-fragment order: [hi: N*32 uint2][lo: N*32 uint2]
__device__ __align__(16) uint2 g_w1[2 * 128 * 32];
__device__ __align__(16) uint2 g_w2[2 * 128 * 32];
__device__ __align__(16) uint2 g_w3[2 * 64 * 32];

// ===================== bf16 split helper ====================================
__device__ __forceinline__ void bsplit(float f, unsigned short& h, unsigned short& l) {
    __nv_bfloat16 bh = __float2bfloat16(f);
    float r = f - __bfloat162float(bh);
    __nv_bfloat16 bl = __float2bfloat16(r);
    h = __bfloat16_as_ushort(bh);
    l = __bfloat16_as_ushort(bl);
}

__device__ __forceinline__ uint4 frag_from_smem(const uint32_t* S, int ks, int lf) {
    int rr = lf >> 2, tg = lf & 3;
    uint4 v;
    v.x = S[rr * SSTR + ks * 8 + tg];
    v.y = S[(rr + 8) * SSTR + ks * 8 + tg];
    v.z = S[rr * SSTR + ks * 8 + 4 + tg];
    v.w = S[(rr + 8) * SSTR + ks * 8 + 4 + tg];
    return v;
}

// ===================== fused prep: init + prepW + detect ====================
__global__ void k_prep(const float* __restrict__ W1, const float* __restrict__ W2,
                       const float* __restrict__ W3, const int* __restrict__ ei) {
    int b = blockIdx.x;
    if (b < 196) {
        int i = b * 256 + threadIdx.x;
        if (i < N_NODES) g_cnt[i] = 0;
        return;
    }
    if (b < 199) {
        int w = b - 196;
        const float* W = (w == 0) ? W1 : (w == 1) ? W2 : W3;
        uint2* dst = (w == 0) ? g_w1 : (w == 1) ? g_w2 : g_w3;
        int N = (w == 2) ? 64 : 128;
        int perProd = N * 32;
        for (int e = threadIdx.x; e < 2 * perProd; e += blockDim.x) {
            int p = e / perProd;
            int rem = e % perProd;
            int ts = rem / 32;
            int l = rem % 32;
            int t = ts / 8, s = ts % 8;
            int n = t * 8 + (l >> 2);
            int k0 = s * 16 + (l & 3) * 2;
            unsigned short v[4], h, lo16;
            int ks[4] = {k0, k0 + 1, k0 + 8, k0 + 9};
#pragma unroll
            for (int q = 0; q < 4; q++) {
                bsplit(W[ks[q] * N + n], h, lo16);
                v[q] = p ? lo16 : h;
            }
            uint2 o;
            o.x = (uint32_t)v[0] | ((uint32_t)v[1] << 16);
            o.y = (uint32_t)v[2] | ((uint32_t)v[3] << 16);
            dst[e] = o;
        }
        return;
    }
    if (threadIdx.x < 32) {
        int lane = threadIdx.x;
        int nzl = (__ldg(&ei[2 * lane + 1]) != 0) | (__ldg(&ei[2 * (lane + 32) + 1]) != 0);
        unsigned m = __ballot_sync(0xFFFFFFFFu, nzl);
        if (lane == 0) g_nz = (m != 0) ? 1 : 0;
    }
}

// x (fp32) -> A-fragment images; smem-staged, coalesced in and out.
__global__ void k_conv(const float* __restrict__ x) {
    __shared__ uint32_t SH[32 * SSTR];
    __shared__ uint32_t SL[32 * SSTR];
    int t = threadIdx.x;
    int rowBase = blockIdx.x * 32;
#pragma unroll
    for (int i = 0; i < 4; i++) {
        int flat = i * 256 + t;
        int r = flat >> 5;
        int q = flat & 31;
        int gr = rowBase + r;
        float4 v = (gr < N_NODES) ? __ldg((const float4*)(x + (size_t)gr * 128) + q)
                                  : make_float4(0.f, 0.f, 0.f, 0.f);
        unsigned short h0, l0, h1, l1, h2, l2, h3, l3;
        bsplit(v.x, h0, l0);
        bsplit(v.y, h1, l1);
        bsplit(v.z, h2, l2);
        bsplit(v.w, h3, l3);
        SH[r * SSTR + 2 * q]     = (uint32_t)h0 | ((uint32_t)h1 << 16);
        SH[r * SSTR + 2 * q + 1] = (uint32_t)h2 | ((uint32_t)h3 << 16);
        SL[r * SSTR + 2 * q]     = (uint32_t)l0 | ((uint32_t)l1 << 16);
        SL[r * SSTR + 2 * q + 1] = (uint32_t)l2 | ((uint32_t)l3 << 16);
    }
    __syncthreads();
#pragma unroll
    for (int j = 0; j < 2; j++) {
        int idx = j * 256 + t;
        int mtL = idx >> 8;
        int rem = idx & 255;
        int ks = rem >> 5, lf = rem & 31;
        int mt = blockIdx.x * 2 + mtL;
        if (mt < MT) {
            size_t gidx = (size_t)(mt * 8 + ks) * 32 + lf;
            g_ahi[gidx] = frag_from_smem(SH + mtL * 16 * SSTR, ks, lf);
            g_alo[gidx] = frag_from_smem(SL + mtL * 16 * SSTR, ks, lf);
        }
    }
}

__device__ __forceinline__ int load_idx(const void* p, long long i, int is64) {
    return is64 ? (int)((const long long*)p)[i] : ((const int*)p)[i];
}

__global__ void k_fillpad(const void* __restrict__ idx, int E) {
    int e = blockIdx.x * blockDim.x + threadIdx.x;
    if (e >= E) return;
    int is64 = (g_nz == 0);
    int s = load_idx(idx, e, is64);
    int d = load_idx(idx, (long long)E + e, is64);
    int pos = atomicAdd(&g_cnt[d], 1);
    if (pos < CAP) g_colp[(size_t)d * CAP + pos] = s;
}

__global__ void k_dinv() {
    int i = blockIdx.x * blockDim.x + threadIdx.x;
    if (i < N_NODES) g_dinv[i] = rsqrtf((float)g_cnt[i] + 1.0f);
}

// ===================== mma helper ===========================================
__device__ __forceinline__ void mma16816(float& d0, float& d1, float& d2, float& d3,
                                         uint32_t a0, uint32_t a1, uint32_t a2, uint32_t a3,
                                         uint32_t b0, uint32_t b1) {
    asm volatile(
        "mma.sync.aligned.m16n8k16.row.col.f32.bf16.bf16.f32 "
        "{%0,%1,%2,%3}, {%4,%5,%6,%7}, {%8,%9}, {%0,%1,%2,%3};"
        : "+f"(d0), "+f"(d1), "+f"(d2), "+f"(d3)
        : "r"(a0), "r"(a1), "r"(a2), "r"(a3), "r"(b0), "r"(b1));
}

// ===================== fragment-image GEMM ==================================
template <int N>
__global__ void __launch_bounds__(256, 2) k_gemm_frag(const uint2* __restrict__ wimg,
                                                      __half* __restrict__ C) {
    constexpr int NSUB = N / 16;
    int tid = threadIdx.x;
    int lane = tid & 31;
    int wid = tid >> 5;
    int wm = wid & 3;
    int wn = wid >> 2;
    int rowBase = blockIdx.x * 128;
    int mtBase = blockIdx.x * 8 + wm * 2;

    const uint2* Bh = wimg;
    const uint2* Bl = wimg + N * 32;

    float acc[2][NSUB][4];
#pragma unroll
    for (int i = 0; i < 2; i++)
#pragma unroll
        for (int j = 0; j < NSUB; j++)
#pragma unroll
            for (int q = 0; q < 4; q++) acc[i][j][q] = 0.f;

#pragma unroll
    for (int ks = 0; ks < 8; ks++) {
        uint4 ah[2], al[2];
#pragma unroll
        for (int i = 0; i < 2; i++) {
            size_t idx = (size_t)((mtBase + i) * 8 + ks) * 32 + lane;
            ah[i] = __ldg(&g_ahi[idx]);
            al[i] = __ldg(&g_alo[idx]);
        }
#pragma unroll
        for (int j = 0; j < NSUB; j++) {
            int ntile = wn * NSUB + j;
            int bidx = (ntile * 8 + ks) * 32 + lane;
            uint2 bh = __ldg(&Bh[bidx]);
            uint2 bl = __ldg(&Bl[bidx]);
#pragma unroll
            for (int i = 0; i < 2; i++) {
                mma16816(acc[i][j][0], acc[i][j][1], acc[i][j][2], acc[i][j][3],
                         ah[i].x, ah[i].y, ah[i].z, ah[i].w, bh.x, bh.y);
                mma16816(acc[i][j][0], acc[i][j][1], acc[i][j][2], acc[i][j][3],
                         ah[i].x, ah[i].y, ah[i].z, ah[i].w, bl.x, bl.y);
                mma16816(acc[i][j][0], acc[i][j][1], acc[i][j][2], acc[i][j][3],
                         al[i].x, al[i].y, al[i].z, al[i].w, bh.x, bh.y);
            }
        }
    }

#pragma unroll
    for (int i = 0; i < 2; i++) {
        int r0 = rowBase + wm * 32 + i * 16 + (lane >> 2);
#pragma unroll
        for (int j = 0; j < NSUB; j++) {
            int col = wn * (N / 2) + j * 8 + (lane & 3) * 2;
            if (r0 < N_NODES)
                *(__half2*)&C[(size_t)r0 * N + col] = __floats2half2_rn(acc[i][j][0], acc[i][j][1]);
            if (r0 + 8 < N_NODES)
                *(__half2*)&C[(size_t)(r0 + 8) * N + col] = __floats2half2_rn(acc[i][j][2], acc[i][j][3]);
        }
    }
}

// ===================== aggregation (shuffle-batched indices) ================
__device__ __forceinline__ void h4_to_f(const uint2 u, float* f) {
    float2 a = __half22float2(*(const __half2*)&u.x);
    float2 b = __half22float2(*(const __half2*)&u.y);
    f[0] = a.x; f[1] = a.y; f[2] = b.x; f[3] = b.y;
}

template <int COLS>
__device__ __forceinline__ void acc_one(const __half* __restrict__ xw, int s, float wgt,
                                        int lane, float* acc) {
    if (COLS == 128) {
        uint2 u = __ldg((const uint2*)(xw + (size_t)s * COLS) + lane);
        float f[4];
        h4_to_f(u, f);
#pragma unroll
        for (int j = 0; j < 4; j++) acc[j] += wgt * f[j];
    } else {
        uint32_t u = __ldg((const uint32_t*)(xw + (size_t)s * COLS) + lane);
        float2 f = __half22float2(*(const __half2*)&u);
        acc[0] += wgt * f.x;
        acc[1] += wgt * f.y;
    }
}

template <int COLS>
__device__ __forceinline__ void acc_four(const __half* __restrict__ xw,
                                         int s0, int s1, int s2, int s3,
                                         float w0, float w1, float w2, float w3,
                                         int lane, float* acc) {
    if (COLS == 128) {
        uint2 u0 = __ldg((const uint2*)(xw + (size_t)s0 * COLS) + lane);
        uint2 u1 = __ldg((const uint2*)(xw + (size_t)s1 * COLS) + lane);
        uint2 u2 = __ldg((const uint2*)(xw + (size_t)s2 * COLS) + lane);
        uint2 u3 = __ldg((const uint2*)(xw + (size_t)s3 * COLS) + lane);
        float f0[4], f1[4], f2[4], f3[4];
        h4_to_f(u0, f0);
        h4_to_f(u1, f1);
        h4_to_f(u2, f2);
        h4_to_f(u3, f3);
#pragma unroll
        for (int j = 0; j < 4; j++)
            acc[j] += w0 * f0[j] + w1 * f1[j] + w2 * f2[j] + w3 * f3[j];
    } else {
        uint32_t u0 = __ldg((const uint32_t*)(xw + (size_t)s0 * COLS) + lane);
        uint32_t u1 = __ldg((const uint32_t*)(xw + (size_t)s1 * COLS) + lane);
        uint32_t u2 = __ldg((const uint32_t*)(xw + (size_t)s2 * COLS) + lane);
        uint32_t u3 = __ldg((const uint32_t*)(xw + (size_t)s3 * COLS) + lane);
        float2 f0 = __half22float2(*(const __half2*)&u0);
        float2 f1 = __half22float2(*(const __half2*)&u1);
        float2 f2 = __half22float2(*(const __half2*)&u2);
        float2 f3 = __half22float2(*(const __half2*)&u3);
        acc[0] += w0 * f0.x + w1 * f1.x + w2 * f2.x + w3 * f3.x;
        acc[1] += w0 * f0.y + w1 * f1.y + w2 * f2.y + w3 * f3.y;
    }
}

// Gather+scale+bias for one row per warp; indices batch-loaded + shuffled.
template <int COLS>
__device__ __forceinline__ void agg_row(int w, int lane, const __half* __restrict__ xw,
                                        const float* __restrict__ bias, float* x) {
    constexpr int V = COLS / 32;
    float di = g_dinv[w];
    int cnt = __ldg(&g_cnt[w]);
    int end = (cnt < CAP) ? cnt : CAP;
    const int* clist = g_colp + (size_t)w * CAP;

    // batch prefetch: one coalesced index load + one parallel dinv gather
    int uA = 0;
    float dA = 0.f;
    if (lane < end) {
        uA = __ldg(&clist[lane]);
        dA = __ldg(&g_dinv[uA]);
    }
    int uB = 0;
    float dB = 0.f;
    if (32 + lane < end) {
        uB = __ldg(&clist[32 + lane]);
        dB = __ldg(&g_dinv[uB]);
    }

    float acc[V];
#pragma unroll
    for (int j = 0; j < V; j++) acc[j] = 0.f;

    int e0 = (end < 32) ? end : 32;
    int k = 0;
    for (; k + 4 <= e0; k += 4) {
        int s0 = __shfl_sync(0xFFFFFFFFu, uA, k);
        int s1 = __shfl_sync(0xFFFFFFFFu, uA, k + 1);
        int s2 = __shfl_sync(0xFFFFFFFFu, uA, k + 2);
        int s3 = __shfl_sync(0xFFFFFFFFu, uA, k + 3);
        float w0 = __shfl_sync(0xFFFFFFFFu, dA, k);
        float w1 = __shfl_sync(0xFFFFFFFFu, dA, k + 1);
        float w2 = __shfl_sync(0xFFFFFFFFu, dA, k + 2);
        float w3 = __shfl_sync(0xFFFFFFFFu, dA, k + 3);
        acc_four<COLS>(xw, s0, s1, s2, s3, w0, w1, w2, w3, lane, acc);
    }
    for (; k < e0; k++) {
        int s0 = __shfl_sync(0xFFFFFFFFu, uA, k);
        float w0 = __shfl_sync(0xFFFFFFFFu, dA, k);
        acc_one<COLS>(xw, s0, w0, lane, acc);
    }
    // rare second batch (deg > 32)
    for (k = 32; k < end; k++) {
        int s0 = __shfl_sync(0xFFFFFFFFu, uB, k - 32);
        float w0 = __shfl_sync(0xFFFFFFFFu, dB, k - 32);
        acc_one<COLS>(xw, s0, w0, lane, acc);
    }

    float di2 = di * di;
    if (V == 4) {
        uint2 us = __ldg((const uint2*)(xw + (size_t)w * COLS) + lane);
        float fs[4];
        h4_to_f(us, fs);
#pragma unroll
        for (int j = 0; j < 4; j++) x[j] = acc[j] * di + di2 * fs[j];
    } else {
        uint32_t us = __ldg((const uint32_t*)(xw + (size_t)w * COLS) + lane);
        float2 fs = __half22float2(*(const __half2*)&us);
        x[0] = acc[0] * di + di2 * fs.x;
        x[1] = acc[1] * di + di2 * fs.y;
    }
#pragma unroll
    for (int j = 0; j < V; j++) x[j] += __ldg(&bias[lane * V + j]);
}

__device__ __forceinline__ void relu_ln_128(float* x, int lane,
                                            const float* __restrict__ gamma,
                                            const float* __restrict__ beta) {
#pragma unroll
    for (int j = 0; j < 4; j++) x[j] = fmaxf(x[j], 0.f);
    float s = 0.f, s2 = 0.f;
#pragma unroll
    for (int j = 0; j < 4; j++) { s += x[j]; s2 += x[j] * x[j]; }
#pragma unroll
    for (int o = 16; o > 0; o >>= 1) {
        s += __shfl_xor_sync(0xFFFFFFFFu, s, o);
        s2 += __shfl_xor_sync(0xFFFFFFFFu, s2, o);
    }
    float mu = s * (1.0f / 128.0f);
    float var = s2 * (1.0f / 128.0f) - mu * mu;
    float inv = rsqrtf(var + EPS);
#pragma unroll
    for (int j = 0; j < 4; j++)
        x[j] = (x[j] - mu) * inv * __ldg(&gamma[lane * 4 + j]) + __ldg(&beta[lane * 4 + j]);
}

// FRAG_OUT agg: 512 threads = 16 rows = one m-tile; coalesced frag writes.
__global__ void __launch_bounds__(512) k_agg_frag(const __half* __restrict__ xw,
                                                  const float* __restrict__ bias,
                                                  const float* __restrict__ gamma,
                                                  const float* __restrict__ beta) {
    __shared__ uint32_t SH[16 * SSTR];
    __shared__ uint32_t SL[16 * SSTR];
    int tid = threadIdx.x;
    int lane = tid & 31;
    int wid = tid >> 5;
    int w = blockIdx.x * 16 + wid;

    float x[4];
    agg_row<128>(w, lane, xw, bias, x);
    relu_ln_128(x, lane, gamma, beta);

    unsigned short h0, l0, h1, l1, h2, l2, h3, l3;
    bsplit(x[0], h0, l0);
    bsplit(x[1], h1, l1);
    bsplit(x[2], h2, l2);
    bsplit(x[3], h3, l3);
    SH[wid * SSTR + 2 * lane]     = (uint32_t)h0 | ((uint32_t)h1 << 16);
    SH[wid * SSTR + 2 * lane + 1] = (uint32_t)h2 | ((uint32_t)h3 << 16);
    SL[wid * SSTR + 2 * lane]     = (uint32_t)l0 | ((uint32_t)l1 << 16);
    SL[wid * SSTR + 2 * lane + 1] = (uint32_t)l2 | ((uint32_t)l3 << 16);
    __syncthreads();

    int mt = blockIdx.x;
    int half = tid >> 8;
    int rem = tid & 255;
    int ks = rem >> 5, lf = rem & 31;
    size_t gidx = (size_t)(mt * 8 + ks) * 32 + lf;
    if (half == 0)
        g_ahi[gidx] = frag_from_smem(SH, ks, lf);
    else
        g_alo[gidx] = frag_from_smem(SL, ks, lf);
}

// final agg (64 cols, fp32 out)
__global__ void k_agg_out(const __half* __restrict__ xw, const float* __restrict__ bias,
                          float* __restrict__ out) {
    int w = (blockIdx.x * blockDim.x + threadIdx.x) >> 5;
    int lane = threadIdx.x & 31;
    if (w >= N_NODES) return;
    float x[2];
    agg_row<64>(w, lane, xw, bias, x);
    *((float2*)(out + (size_t)w * 64) + lane) = make_float2(x[0], x[1]);
}

// ===================== launch ===============================================
extern "C" void kernel_launch(void* const* d_in, const int* in_sizes, int n_in,
                              void* d_out, int out_size) {
    const float* x  = (const float*)d_in[0];
    const void*  ei = d_in[1];
    const float* W1 = (const float*)d_in[2];
    const float* b1 = (const float*)d_in[3];
    const float* W2 = (const float*)d_in[4];
    const float* b2 = (const float*)d_in[5];
    const float* W3 = (const float*)d_in[6];
    const float* b3 = (const float*)d_in[7];
    const float* g1 = (const float*)d_in[8];
    const float* be1 = (const float*)d_in[9];
    const float* g2 = (const float*)d_in[10];
    const float* be2 = (const float*)d_in[11];
    float* out = (float*)d_out;
    int E = in_sizes[1] / 2;

    __half *hX, *hC;
    uint2 *w1i, *w2i, *w3i;
    cudaGetSymbolAddress((void**)&hX, g_h128);
    cudaGetSymbolAddress((void**)&hC, g_h64);
    cudaGetSymbolAddress((void**)&w1i, g_w1);
    cudaGetSymbolAddress((void**)&w2i, g_w2);
    cudaGetSymbolAddress((void**)&w3i, g_w3);

    cudaStream_t s2;
    cudaStreamCreateWithFlags(&s2, cudaStreamNonBlocking);
    cudaEvent_t evFork, evJoin;
    cudaEventCreateWithFlags(&evFork, cudaEventDisableTiming);
    cudaEventCreateWithFlags(&evJoin, cudaEventDisableTiming);

    int gemmGrid = (N_NODES + 127) / 128;  // 391

    // prep feeds both branches (cnt init for adjacency, W images for gemm)
    k_prep<<<200, 256>>>(W1, W2, W3, (const int*)ei);
    cudaEventRecord(evFork, 0);
    cudaStreamWaitEvent(s2, evFork, 0);

    // branch A (s2): single-pass padded adjacency + dinv
    k_fillpad<<<(E + 255) / 256, 256, 0, s2>>>(ei, E);
    k_dinv<<<(N_NODES + 255) / 256, 256, 0, s2>>>();
    cudaEventRecord(evJoin, s2);

    // branch B (default): x -> fragment images (smem-staged), then gemm1
    k_conv<<<1563, 256>>>(x);
    k_gemm_frag<128><<<gemmGrid, 256>>>(w1i, hX);

    // join: agg1 needs adjacency + gemm1
    cudaStreamWaitEvent(0, evJoin, 0);
    k_agg_frag<<<3125, 512>>>(hX, b1, g1, be1);
    // layer 2
    k_gemm_frag<128><<<gemmGrid, 256>>>(w2i, hX);
    k_agg_frag<<<3125, 512>>>(hX, b2, g2, be2);
    // layer 3
    k_gemm_frag<64><<<gemmGrid, 256>>>(w3i, hC);
    k_agg_out<<<6250, 256>>>(hC, b3, out);
}